// round 2
// baseline (speedup 1.0000x reference)
#include <cuda_runtime.h>
#include <math_constants.h>

#define NPTS 8192
#define BATCH 4
#define KNNK 10

// ---------------- scratch arena (no allocation allowed) ----------------
// offsets in floats, all 4KB-aligned
#define O_X0     0u           // 4*8192*6      = 196608
#define O_IDX    196608u      // 4*8192*10 int = 327680
#define O_X1     524288u      // 4*8192*64     = 2097152
#define O_X2     2621440u
#define O_X3     4718592u
#define O_X4     6815744u     // 4*8192*192    = 6291456
#define O_X5     13107200u    // 4*8192*1024   = 33554432
#define O_PMAX   46661632u    // 4*32*1024
#define O_X5MAX  46792704u    // 4*1024
#define O_BIAS   46796800u    // 4*256
#define O_Y1     46797824u    // 4*8192*256
#define O_Y2     55186432u
#define O_Y3     63575040u    // 4*8192*128
#define SCRATCH_FLOATS 67769344u

__device__ __align__(16) float g_scratch[SCRATCH_FLOATS];

// ---------------- build x0 = concat(targets, targets) ----------------
__global__ void build_x0_kernel(const float* __restrict__ t, float* __restrict__ x0) {
    int i = blockIdx.x * blockDim.x + threadIdx.x;
    if (i < BATCH * NPTS * 6) {
        int pt = i / 6, c = i % 6;
        x0[i] = t[pt * 3 + (c < 3 ? c : c - 3)];
    }
}

// ---------------- fused KNN (distance + top-10 selection) ----------------
// grid (NPTS/128, BATCH), block 128. Each thread owns one query point.
template<int C>
__global__ void knn_kernel(const float* __restrict__ x, int* __restrict__ idxout) {
    __shared__ float tile[128 * C];
    __shared__ float tnorm[128];
    const int b = blockIdx.y;
    const int q = blockIdx.x * 128 + threadIdx.x;
    const float* xb = x + (size_t)b * NPTS * C;

    float qf[C];
    float qn = 0.f;
    #pragma unroll
    for (int c = 0; c < C; c++) { qf[c] = xb[q * C + c]; qn = fmaf(qf[c], qf[c], qn); }

    float bd[KNNK]; int bi[KNNK];
    #pragma unroll
    for (int i = 0; i < KNNK; i++) { bd[i] = CUDART_INF_F; bi[i] = 0; }

    for (int t0 = 0; t0 < NPTS; t0 += 128) {
        __syncthreads();
        for (int i = threadIdx.x; i < 128 * C; i += 128) tile[i] = xb[t0 * C + i];
        __syncthreads();
        {   // norm of tile point threadIdx.x
            float s = 0.f;
            #pragma unroll
            for (int c = 0; c < C; c++) {
                float v = tile[threadIdx.x * C + c];
                s = fmaf(v, v, s);
            }
            tnorm[threadIdx.x] = s;
        }
        __syncthreads();

        for (int j = 0; j < 128; j++) {
            float dot;
            if constexpr (C % 4 == 0) {
                float d0 = 0.f, d1 = 0.f, d2 = 0.f, d3 = 0.f;
                #pragma unroll
                for (int c = 0; c < C; c += 4) {
                    d0 = fmaf(qf[c + 0], tile[j * C + c + 0], d0);
                    d1 = fmaf(qf[c + 1], tile[j * C + c + 1], d1);
                    d2 = fmaf(qf[c + 2], tile[j * C + c + 2], d2);
                    d3 = fmaf(qf[c + 3], tile[j * C + c + 3], d3);
                }
                dot = (d0 + d1) + (d2 + d3);
            } else {
                float d0 = 0.f, d1 = 0.f;
                #pragma unroll
                for (int c = 0; c < C; c += 2) {
                    d0 = fmaf(qf[c + 0], tile[j * C + c + 0], d0);
                    d1 = fmaf(qf[c + 1], tile[j * C + c + 1], d1);
                }
                dot = d0 + d1;
            }
            float d = qn + tnorm[j] - 2.f * dot;
            if (d < bd[KNNK - 1]) {
                bd[KNNK - 1] = d; bi[KNNK - 1] = t0 + j;
                #pragma unroll
                for (int s = KNNK - 1; s > 0; s--) {
                    if (bd[s] < bd[s - 1]) {
                        float td = bd[s]; bd[s] = bd[s - 1]; bd[s - 1] = td;
                        int   ti = bi[s]; bi[s] = bi[s - 1]; bi[s - 1] = ti;
                    }
                }
            }
        }
    }
    int* o = idxout + ((size_t)b * NPTS + q) * KNNK;
    #pragma unroll
    for (int i = 0; i < KNNK; i++) o[i] = bi[i];
}

// ---------------- edge conv: shared-MLP over edge features + max over k ----------------
// block 512 = 16 warps, one point per warp, 2 output channels per lane.
template<int C, bool TWO>
__global__ void edge_conv_kernel(const float* __restrict__ x, const int* __restrict__ knn,
                                 const float* __restrict__ w1, const float* __restrict__ w2,
                                 const float* __restrict__ pa, int ai1, int ai2,
                                 float* __restrict__ out) {
    constexpr int F = 2 * C;
    constexpr int PPB = 16;
    extern __shared__ float sm[];
    float* ws1 = sm;                         // F*64
    float* ws2 = ws1 + F * 64;               // 4096 if TWO
    float* fb  = ws2 + (TWO ? 4096 : 0);     // PPB*F
    float* h1b = fb + PPB * F;               // PPB*64 if TWO

    int tid = threadIdx.x;
    for (int i = tid; i < F * 64; i += 512) ws1[i] = w1[i];
    if (TWO) for (int i = tid; i < 4096; i += 512) ws2[i] = w2[i];
    float a1 = pa[ai1];
    float a2 = TWO ? pa[ai2] : 0.f;
    __syncthreads();

    int g = tid >> 5, lt = tid & 31;
    size_t pt = (size_t)blockIdx.x * PPB + g;
    int b = (int)(pt / NPTS);
    int n = (int)(pt % NPTS);
    const float* xb = x + (size_t)b * NPTS * C;
    const int* nbr = knn + pt * KNNK;
    float* f  = fb + g * F;
    float* h1 = h1b + g * 64;
    int ch = lt * 2;

    // center features (persist across neighbors)
    for (int c = lt; c < C; c += 32) f[C + c] = xb[n * C + c];

    float mx0 = -CUDART_INF_F, mx1 = -CUDART_INF_F;
    for (int j = 0; j < KNNK; j++) {
        int nb = nbr[j];
        __syncwarp();
        for (int c = lt; c < C; c += 32) f[c] = xb[nb * C + c] - f[C + c];
        __syncwarp();
        float s0 = 0.f, s1 = 0.f;
        #pragma unroll 8
        for (int c = 0; c < F; c++) {
            float fv = f[c];
            float2 wv = *(const float2*)(ws1 + c * 64 + ch);
            s0 = fmaf(fv, wv.x, s0);
            s1 = fmaf(fv, wv.y, s1);
        }
        float h0  = s0 >= 0.f ? s0 : a1 * s0;
        float hh1 = s1 >= 0.f ? s1 : a1 * s1;
        if (TWO) {
            h1[ch] = h0; h1[ch + 1] = hh1;
            __syncwarp();
            float t0 = 0.f, t1 = 0.f;
            #pragma unroll 8
            for (int c = 0; c < 64; c++) {
                float hv = h1[c];
                float2 wv = *(const float2*)(ws2 + c * 64 + ch);
                t0 = fmaf(hv, wv.x, t0);
                t1 = fmaf(hv, wv.y, t1);
            }
            h0  = t0 >= 0.f ? t0 : a2 * t0;
            hh1 = t1 >= 0.f ? t1 : a2 * t1;
        }
        mx0 = fmaxf(mx0, h0);
        mx1 = fmaxf(mx1, hh1);
    }
    out[pt * 64 + ch]     = mx0;
    out[pt * 64 + ch + 1] = mx1;
}

// ---------------- concat x4 = [x1|x2|x3] ----------------
__global__ void concat_x4_kernel(const float* __restrict__ x1, const float* __restrict__ x2,
                                 const float* __restrict__ x3, float* __restrict__ x4) {
    int i = blockIdx.x * 256 + threadIdx.x;
    if (i < BATCH * NPTS * 192) {
        int pt = i / 192, c = i % 192;
        float v = (c < 64) ? x1[pt * 64 + c]
                : (c < 128) ? x2[pt * 64 + c - 64]
                : x3[pt * 64 + c - 128];
        x4[i] = v;
    }
}

// ---------------- SGEMM + per-batch bias + PReLU epilogue ----------------
// BM=64 BN=64 BK=16, 128 threads, per-thread 8x4
__global__ void gemm_prelu_kernel(const float* __restrict__ A, const float* __restrict__ B,
                                  float* __restrict__ C, const float* __restrict__ bias,
                                  const float* __restrict__ pa, int aidx,
                                  int K, int Nc) {
    __shared__ float As[16][64];
    __shared__ float Bs[16][64];
    int tid = threadIdx.x;
    int tx = tid & 15, ty = tid >> 4;
    int m0 = blockIdx.x * 64, n0 = blockIdx.y * 64;

    float acc[8][4];
    #pragma unroll
    for (int r = 0; r < 8; r++)
        #pragma unroll
        for (int c = 0; c < 4; c++) acc[r][c] = 0.f;

    for (int k0 = 0; k0 < K; k0 += 16) {
        #pragma unroll
        for (int l = 0; l < 2; l++) {
            int i = tid * 2 + l;
            int m = i >> 2, kc = (i & 3) * 4;
            float4 v = *(const float4*)(A + (size_t)(m0 + m) * K + k0 + kc);
            As[kc + 0][m] = v.x; As[kc + 1][m] = v.y;
            As[kc + 2][m] = v.z; As[kc + 3][m] = v.w;
            int kb = i >> 4, nb = (i & 15) * 4;
            float4 w = *(const float4*)(B + (size_t)(k0 + kb) * Nc + n0 + nb);
            *(float4*)(&Bs[kb][nb]) = w;
        }
        __syncthreads();
        #pragma unroll
        for (int kk = 0; kk < 16; kk++) {
            float a[8], bb[4];
            #pragma unroll
            for (int r = 0; r < 8; r++) a[r] = As[kk][ty * 8 + r];
            #pragma unroll
            for (int c = 0; c < 4; c++) bb[c] = Bs[kk][tx * 4 + c];
            #pragma unroll
            for (int r = 0; r < 8; r++)
                #pragma unroll
                for (int c = 0; c < 4; c++)
                    acc[r][c] = fmaf(a[r], bb[c], acc[r][c]);
        }
        __syncthreads();
    }

    float al = pa[aidx];
    #pragma unroll
    for (int r = 0; r < 8; r++) {
        size_t m = (size_t)m0 + ty * 8 + r;
        int n = n0 + tx * 4;
        float4 v;
        float bv0 = 0.f, bv1 = 0.f, bv2 = 0.f, bv3 = 0.f;
        if (bias) {
            const float* brow = bias + (m >> 13) * Nc;
            bv0 = brow[n]; bv1 = brow[n + 1]; bv2 = brow[n + 2]; bv3 = brow[n + 3];
        }
        float e0 = acc[r][0] + bv0, e1 = acc[r][1] + bv1;
        float e2 = acc[r][2] + bv2, e3 = acc[r][3] + bv3;
        v.x = e0 >= 0.f ? e0 : al * e0;
        v.y = e1 >= 0.f ? e1 : al * e1;
        v.z = e2 >= 0.f ? e2 : al * e2;
        v.w = e3 >= 0.f ? e3 : al * e3;
        *(float4*)(C + m * Nc + n) = v;
    }
}

// ---------------- global max over N (two stage) + bias from w7 tail ----------------
__global__ void max1_kernel(const float* __restrict__ x5, float* __restrict__ pmax) {
    int b = blockIdx.y, chunk = blockIdx.x, c = threadIdx.x; // block 1024
    const float* p = x5 + ((size_t)b * NPTS + (size_t)chunk * 256) * 1024 + c;
    float m = -CUDART_INF_F;
    for (int n = 0; n < 256; n++) m = fmaxf(m, p[(size_t)n * 1024]);
    pmax[((size_t)b * 32 + chunk) * 1024 + c] = m;
}
__global__ void max2_kernel(const float* __restrict__ pmax, float* __restrict__ x5max) {
    int b = blockIdx.x, c = threadIdx.x;
    float m = -CUDART_INF_F;
    for (int k = 0; k < 32; k++) m = fmaxf(m, pmax[((size_t)b * 32 + k) * 1024 + c]);
    x5max[b * 1024 + c] = m;
}
__global__ void bias_kernel(const float* __restrict__ x5max, const float* __restrict__ w7,
                            float* __restrict__ bias) {
    int b = blockIdx.x, j = threadIdx.x; // block 256
    float s = 0.f;
    for (int c = 0; c < 1024; c++)
        s = fmaf(x5max[b * 1024 + c], w7[(size_t)(192 + c) * 256 + j], s);
    bias[b * 256 + j] = s;
}

// ---------------- final 128->2 layer, warp per point ----------------
__global__ void final_kernel(const float* __restrict__ y3, const float* __restrict__ w10,
                             const float* __restrict__ pa, float* __restrict__ out) {
    __shared__ float ws[256];
    int tid = threadIdx.x; // 128
    ws[tid * 2] = w10[tid * 2];
    ws[tid * 2 + 1] = w10[tid * 2 + 1];
    __syncthreads();
    int warp = tid >> 5, lane = tid & 31;
    size_t pt = (size_t)blockIdx.x * 4 + warp;
    const float* row = y3 + pt * 128;
    float s0 = 0.f, s1 = 0.f;
    for (int c = lane; c < 128; c += 32) {
        float v = row[c];
        s0 = fmaf(v, ws[c * 2], s0);
        s1 = fmaf(v, ws[c * 2 + 1], s1);
    }
    #pragma unroll
    for (int o = 16; o > 0; o >>= 1) {
        s0 += __shfl_down_sync(0xffffffffu, s0, o);
        s1 += __shfl_down_sync(0xffffffffu, s1, o);
    }
    if (lane == 0) {
        float a = pa[9];
        out[pt * 2]     = s0 >= 0.f ? s0 : a * s0;
        out[pt * 2 + 1] = s1 >= 0.f ? s1 : a * s1;
    }
}

// ---------------- host orchestration ----------------
extern "C" void kernel_launch(void* const* d_in, const int* in_sizes, int n_in,
                              void* d_out, int out_size) {
    const float* targets = (const float*)d_in[0];
    const float* w[10];
    for (int i = 0; i < 10; i++) w[i] = (const float*)d_in[1 + i];
    const float* pa = (const float*)d_in[11];
    float* out = (float*)d_out;

    float* base = nullptr;
    cudaGetSymbolAddress((void**)&base, g_scratch);
    float* x0    = base + O_X0;
    int*   idx   = (int*)(base + O_IDX);
    float* x1    = base + O_X1;
    float* x2    = base + O_X2;
    float* x3    = base + O_X3;
    float* x4    = base + O_X4;
    float* x5    = base + O_X5;
    float* pmax  = base + O_PMAX;
    float* x5max = base + O_X5MAX;
    float* bias  = base + O_BIAS;
    float* y1    = base + O_Y1;
    float* y2    = base + O_Y2;
    float* y3    = base + O_Y3;

    // dynamic smem sizes (bytes)
    const int smem6t  = (12 * 64 + 4096 + 16 * 12 + 16 * 64) * 4;        // 24320
    const int smem64t = (128 * 64 + 4096 + 16 * 128 + 16 * 64) * 4;      // 61440
    const int smem64f = (128 * 64 + 16 * 128 + 16 * 64) * 4;             // 45056 (ws2 unused but layout keeps h1b slot)

    cudaFuncSetAttribute(edge_conv_kernel<64, true>,
                         cudaFuncAttributeMaxDynamicSharedMemorySize, smem64t);

    build_x0_kernel<<<(BATCH * NPTS * 6 + 255) / 256, 256>>>(targets, x0);

    knn_kernel<6><<<dim3(NPTS / 128, BATCH), 128>>>(x0, idx);
    edge_conv_kernel<6, true><<<BATCH * NPTS / 16, 512, smem6t>>>(x0, idx, w[0], w[1], pa, 0, 1, x1);

    knn_kernel<64><<<dim3(NPTS / 128, BATCH), 128>>>(x1, idx);
    edge_conv_kernel<64, true><<<BATCH * NPTS / 16, 512, smem64t>>>(x1, idx, w[2], w[3], pa, 2, 3, x2);

    knn_kernel<64><<<dim3(NPTS / 128, BATCH), 128>>>(x2, idx);
    edge_conv_kernel<64, false><<<BATCH * NPTS / 16, 512, smem64f>>>(x2, idx, w[4], nullptr, pa, 4, 4, x3);

    concat_x4_kernel<<<(BATCH * NPTS * 192 + 255) / 256, 256>>>(x1, x2, x3, x4);

    // x5 = prelu(x4 @ w6), then global max over N per batch
    gemm_prelu_kernel<<<dim3(BATCH * NPTS / 64, 1024 / 64), 128>>>(x4, w[5], x5, nullptr, pa, 5, 192, 1024);
    max1_kernel<<<dim3(32, BATCH), 1024>>>(x5, pmax);
    max2_kernel<<<BATCH, 1024>>>(pmax, x5max);
    bias_kernel<<<BATCH, 256>>>(x5max, w[6], bias);

    // y1 = prelu(x4 @ w7[:192] + x5max @ w7[192:])
    gemm_prelu_kernel<<<dim3(BATCH * NPTS / 64, 256 / 64), 128>>>(x4, w[6], y1, bias, pa, 6, 192, 256);
    // y2 = prelu(y1 @ w8)
    gemm_prelu_kernel<<<dim3(BATCH * NPTS / 64, 256 / 64), 128>>>(y1, w[7], y2, nullptr, pa, 7, 256, 256);
    // y3 = prelu(y2 @ w9)
    gemm_prelu_kernel<<<dim3(BATCH * NPTS / 64, 128 / 64), 128>>>(y2, w[8], y3, nullptr, pa, 8, 256, 128);
    // out = prelu(y3 @ w10)
    final_kernel<<<BATCH * NPTS / 4, 128>>>(y3, w[9], pa, out);

    (void)in_sizes; (void)n_in; (void)out_size;
}